// round 1
// baseline (speedup 1.0000x reference)
#include <cuda_runtime.h>
#include <cuda_bf16.h>

#define NTAGS 64
#define LOG2E 1.4426950408889634f
#define LN2   0.69314718055994531f

__device__ __forceinline__ float fast_ex2(float x) {
    float r; asm("ex2.approx.ftz.f32 %0, %1;" : "=f"(r) : "f"(x)); return r;
}
__device__ __forceinline__ float fast_lg2(float x) {
    float r; asm("lg2.approx.ftz.f32 %0, %1;" : "=f"(r) : "f"(x)); return r;
}
__device__ __forceinline__ void fma2(unsigned long long& d, unsigned long long a, unsigned long long b) {
    asm("fma.rn.f32x2 %0, %1, %2, %0;" : "+l"(d) : "l"(a), "l"(b));
}
__device__ __forceinline__ unsigned long long add2(unsigned long long a, unsigned long long b) {
    unsigned long long r; asm("add.rn.f32x2 %0, %1, %2;" : "=l"(r) : "l"(a), "l"(b)); return r;
}
__device__ __forceinline__ unsigned long long pack2(float x, float y) {
    unsigned long long r; asm("mov.b64 %0, {%1, %2};" : "=l"(r) : "f"(x), "f"(y)); return r;
}
__device__ __forceinline__ float2 unpack2(unsigned long long v) {
    float2 f; asm("mov.b64 {%0, %1}, %2;" : "=f"(f.x), "=f"(f.y) : "l"(v)); return f;
}

// One CTA handles TWO batch elements (b0, b1). 64 threads; thread i owns tag i.
// State score[i] is kept per-thread; the exp(score - M) vector is exchanged via
// double-buffered shared memory once per time step (single __syncthreads/step).
// exp(trans) row i is cached in 128 registers as duplicated f32x2 pairs so a
// single fma.rn.f32x2 advances both batches at once.
__global__ __launch_bounds__(64, 4)
void crf_fwd_kernel(const float* __restrict__ h, const float* __restrict__ trans,
                    const int* __restrict__ lengths, float* __restrict__ out,
                    int B, int T)
{
    const int i = threadIdx.x;                    // tag index 0..63
    const int b0 = blockIdx.x * 2;
    const bool has1 = (b0 + 1 < B);
    const int b1 = has1 ? (b0 + 1) : b0;

    __shared__ __align__(16) unsigned long long pbuf[2][NTAGS]; // packed (p_b0, p_b1)
    __shared__ float2 mbuf[2];                                   // lag-1 scale broadcast
    __shared__ float2 red[2];                                    // epilogue reductions

    // Cache E[i][j] = exp(trans[i][j]) duplicated into f32x2 pairs (128 regs).
    unsigned long long rowp[NTAGS];
    #pragma unroll
    for (int j = 0; j < NTAGS; j++) {
        float e = fast_ex2(trans[i * NTAGS + j] * LOG2E);
        rowp[j] = pack2(e, e);
    }

    const int len0 = lengths[b0];
    const int len1 = has1 ? lengths[b1] : len0;
    const int tmax = max(len0, len1);

    // init: START_TAG = N-2 gets 0, everything else NEG_INF
    float s0 = (i == NTAGS - 2) ? 0.0f : -10000.0f;
    float s1 = s0;
    float M0 = 0.0f, M1 = 0.0f;       // running scale offsets (lag-1 score[0])

    if (i == 0) { mbuf[0] = make_float2(0.f, 0.f); mbuf[1] = make_float2(0.f, 0.f); }
    __syncthreads();

    const float* __restrict__ hp0 = h + (size_t)b0 * T * NTAGS + i;
    const float* __restrict__ hp1 = h + (size_t)b1 * T * NTAGS + i;

    float e0 = hp0[0];
    float e1 = hp1[0];

    int buf = 0;
    for (int t = 0; t < tmax; t++) {
        // p[i] = exp(score[i] - M), packed for both batches
        float p0 = fast_ex2((s0 - M0) * LOG2E);
        float p1 = fast_ex2((s1 - M1) * LOG2E);
        pbuf[buf][i] = pack2(p0, p1);
        __syncthreads();

        // prefetch next step's emissions (off critical path)
        float en0 = 0.f, en1 = 0.f;
        if (t + 1 < tmax) { en0 = hp0[NTAGS]; en1 = hp1[NTAGS]; }
        hp0 += NTAGS; hp1 += NTAGS;

        // lag-1 scale broadcast: written by thread 0 last iteration,
        // ordered by the barrier above; consumed starting NEXT iteration.
        float2 mlag = mbuf[buf ^ 1];

        // dot(E_row_i, p): 32x LDS.128 (broadcast) + 64x FFMA2, 4 accumulators
        const ulonglong2* P = reinterpret_cast<const ulonglong2*>(pbuf[buf]);
        unsigned long long a0 = 0ull, a1 = 0ull, a2 = 0ull, a3 = 0ull;
        #pragma unroll
        for (int j = 0; j < NTAGS / 2; j += 2) {
            ulonglong2 q0 = P[j];
            ulonglong2 q1 = P[j + 1];
            fma2(a0, rowp[2 * j],     q0.x);
            fma2(a1, rowp[2 * j + 1], q0.y);
            fma2(a2, rowp[2 * j + 2], q1.x);
            fma2(a3, rowp[2 * j + 3], q1.y);
        }
        float2 S = unpack2(add2(add2(a0, a1), add2(a2, a3)));

        float news0 = e0 + M0 + LN2 * fast_lg2(S.x);
        float news1 = e1 + M1 + LN2 * fast_lg2(S.y);
        if (t < len0) s0 = news0;     // mask: freeze score past length
        if (t < len1) s1 = news1;

        if (i == 0) mbuf[buf] = make_float2(s0, s1);   // scale for iter t+2's read (lag-1 use)

        M0 = mlag.x; M1 = mlag.y;
        e0 = en0; e1 = en1;
        buf ^= 1;
    }

    // terminal transition to END tag (row N-1), then exact logsumexp
    float te = trans[(NTAGS - 1) * NTAGS + i];
    float x0 = s0 + te, x1 = s1 + te;

    float m0 = x0, m1 = x1;
    #pragma unroll
    for (int o = 16; o > 0; o >>= 1) {
        m0 = fmaxf(m0, __shfl_xor_sync(0xffffffffu, m0, o));
        m1 = fmaxf(m1, __shfl_xor_sync(0xffffffffu, m1, o));
    }
    const int w = i >> 5;
    if ((i & 31) == 0) red[w] = make_float2(m0, m1);
    __syncthreads();
    m0 = fmaxf(red[0].x, red[1].x);
    m1 = fmaxf(red[0].y, red[1].y);

    float y0 = fast_ex2((x0 - m0) * LOG2E);
    float y1 = fast_ex2((x1 - m1) * LOG2E);
    #pragma unroll
    for (int o = 16; o > 0; o >>= 1) {
        y0 += __shfl_xor_sync(0xffffffffu, y0, o);
        y1 += __shfl_xor_sync(0xffffffffu, y1, o);
    }
    __syncthreads();   // red reuse
    if ((i & 31) == 0) red[w] = make_float2(y0, y1);
    __syncthreads();

    if (i == 0) {
        out[b0] = m0 + LN2 * fast_lg2(red[0].x + red[1].x);
        if (has1) out[b0 + 1] = m1 + LN2 * fast_lg2(red[0].y + red[1].y);
    }
}

extern "C" void kernel_launch(void* const* d_in, const int* in_sizes, int n_in,
                              void* d_out, int out_size)
{
    const float* h       = (const float*)d_in[0];   // [B, T, N] f32
    const float* trans   = (const float*)d_in[1];   // [N, N]    f32
    const int*   lengths = (const int*)d_in[2];     // [B]       i32
    float*       out     = (float*)d_out;           // [B]       f32

    const int B = in_sizes[2];
    const int T = in_sizes[0] / (B * NTAGS);

    const int nblk = (B + 1) / 2;
    crf_fwd_kernel<<<nblk, NTAGS>>>(h, trans, lengths, out, B, T);
}